// round 1
// baseline (speedup 1.0000x reference)
#include <cuda_runtime.h>
#include <math.h>

#define B_ 64
#define H_ 4
#define N_ 16384
#define W_ 64
#define D_ 1024
#define P_ 70

// Scratch (device globals: allocation-free rule)
__device__ float g_ebuf[B_ * H_ * N_];   // exp(beta * cos_sim), 16 MB
__device__ float g_kv[B_ * H_ * W_];     // key * beta / ||key||
__device__ float g_hp[B_ * H_ * 8];      // gate, sh0, sh1, sh2, gamma
__device__ float g_sum[B_ * H_];         // softmax denominators (atomic)

__device__ __forceinline__ float softplusf(float x) {
    return x > 20.f ? x : log1pf(__expf(x));
}

// ---------------------------------------------------------------------------
// Kernel A: params GEMM (B x 280 x 1024) + activations. One block per (b,h).
// ---------------------------------------------------------------------------
__global__ __launch_bounds__(256) void kparams(const float* __restrict__ cs,
                                               const float* __restrict__ Wr,
                                               const float* __restrict__ br) {
    int bh = blockIdx.x;
    int b = bh >> 2, h = bh & 3;
    __shared__ float s_cs[D_];
    __shared__ float ps[P_];
    __shared__ float der[8];
    int tid = threadIdx.x;

    for (int k = tid; k < D_; k += 256) s_cs[k] = cs[b * D_ + k];
    __syncthreads();

    int wp = tid >> 5, l = tid & 31;
    for (int p = wp; p < P_; p += 8) {
        int r = h * P_ + p;
        const float* Wrow = Wr + (size_t)r * D_;
        float acc = 0.f;
        #pragma unroll 8
        for (int k = l; k < D_; k += 32) acc = fmaf(Wrow[k], s_cs[k], acc);
        #pragma unroll
        for (int o = 16; o; o >>= 1) acc += __shfl_xor_sync(0xffffffffu, acc, o);
        if (l == 0) ps[p] = acc + br[r];
    }
    __syncthreads();

    if (tid == 0) {
        float kn2 = 0.f;
        #pragma unroll
        for (int i = 0; i < W_; i++) kn2 = fmaf(ps[i], ps[i], kn2);
        float knorm = fmaxf(sqrtf(kn2), 1e-8f);
        float beta = softplusf(ps[W_]);
        der[5] = beta / knorm;
        der[0] = 1.f / (1.f + __expf(-ps[W_ + 1]));            // gate
        float m = fmaxf(ps[W_ + 2], fmaxf(ps[W_ + 3], ps[W_ + 4]));
        float e0 = __expf(ps[W_ + 2] - m);
        float e1 = __expf(ps[W_ + 3] - m);
        float e2 = __expf(ps[W_ + 4] - m);
        float si = 1.f / (e0 + e1 + e2);
        der[1] = e0 * si; der[2] = e1 * si; der[3] = e2 * si;   // shift
        der[4] = 1.f + softplusf(ps[W_ + 5]);                   // gamma
        g_sum[bh] = 0.f;   // re-zero accumulator every replay (deterministic)
    }
    __syncthreads();
    if (tid < W_) g_kv[bh * W_ + tid] = ps[tid] * der[5];
    if (tid < 5)  g_hp[bh * 8 + tid] = der[tid];
}

// ---------------------------------------------------------------------------
// Kernel B: stream memory once. 1 thread = 1 memory row (64 floats, smem,
// padded 65 -> conflict-free). Computes row norm + 4 head dots, writes exp()
// to g_ebuf, atomically accumulates softmax denominators.
// ---------------------------------------------------------------------------
__global__ __launch_bounds__(128) void kdots(const float* __restrict__ mem) {
    __shared__ float sm[128 * 65];
    __shared__ float skv[H_ * W_];
    __shared__ float sred[16];
    int b = blockIdx.y;
    int n0 = blockIdx.x * 128;
    int tid = threadIdx.x;

    for (int i = tid; i < H_ * W_; i += 128) skv[i] = g_kv[b * (H_ * W_) + i];

    const float4* src = (const float4*)(mem + ((size_t)b * N_ + n0) * W_);
    #pragma unroll
    for (int j = 0; j < 16; j++) {
        int f = j * 128 + tid;           // float4 index in tile
        float4 v = src[f];
        int row = f >> 4;
        int c = (f & 15) << 2;
        float* d = &sm[row * 65 + c];
        d[0] = v.x; d[1] = v.y; d[2] = v.z; d[3] = v.w;
    }
    __syncthreads();

    float ssq = 0.f, d0 = 0.f, d1 = 0.f, d2 = 0.f, d3 = 0.f;
    const float* mr = &sm[tid * 65];
    #pragma unroll
    for (int w = 0; w < W_; w++) {
        float m = mr[w];
        ssq = fmaf(m, m, ssq);
        d0 = fmaf(skv[w],            m, d0);
        d1 = fmaf(skv[W_ + w],       m, d1);
        d2 = fmaf(skv[2 * W_ + w],   m, d2);
        d3 = fmaf(skv[3 * W_ + w],   m, d3);
    }
    float inv = 1.f / fmaxf(sqrtf(ssq), 1e-8f);
    float e0 = __expf(d0 * inv);
    float e1 = __expf(d1 * inv);
    float e2 = __expf(d2 * inv);
    float e3 = __expf(d3 * inv);

    size_t o = (size_t)b * H_ * N_ + n0 + tid;
    g_ebuf[o]          = e0;
    g_ebuf[o + N_]     = e1;
    g_ebuf[o + 2 * N_] = e2;
    g_ebuf[o + 3 * N_] = e3;

    float s0 = e0, s1 = e1, s2 = e2, s3 = e3;
    #pragma unroll
    for (int off = 16; off; off >>= 1) {
        s0 += __shfl_xor_sync(0xffffffffu, s0, off);
        s1 += __shfl_xor_sync(0xffffffffu, s1, off);
        s2 += __shfl_xor_sync(0xffffffffu, s2, off);
        s3 += __shfl_xor_sync(0xffffffffu, s3, off);
    }
    if ((tid & 31) == 0) {
        int wp = tid >> 5;
        sred[wp * 4 + 0] = s0; sred[wp * 4 + 1] = s1;
        sred[wp * 4 + 2] = s2; sred[wp * 4 + 3] = s3;
    }
    __syncthreads();
    if (tid < 4) {
        float t = sred[tid] + sred[4 + tid] + sred[8 + tid] + sred[12 + tid];
        atomicAdd(&g_sum[b * 4 + tid], t);
    }
}

// ---------------------------------------------------------------------------
// Kernel C: one (b,h) row per block. gate-mix -> circular shift (smem) ->
// pow(gamma) -> renormalize. Scalar n = k*1024+tid mapping: every access
// coalesced / bank-conflict-free.
// ---------------------------------------------------------------------------
__global__ __launch_bounds__(1024) void kfinish(const float* __restrict__ prev,
                                                float* __restrict__ out) {
    extern __shared__ float sg[];     // N_ floats
    __shared__ float sr[33];
    int bh = blockIdx.x;
    int tid = threadIdx.x;

    const float* hp = &g_hp[bh * 8];
    float gate = hp[0], sh0 = hp[1], sh1 = hp[2], sh2 = hp[3], gamma = hp[4];
    float invS = 1.f / g_sum[bh];
    float a = gate * invS;
    float om = 1.f - gate;

    size_t base = (size_t)bh * N_;
    const float* e = g_ebuf + base;
    const float* p = prev + base;

    #pragma unroll
    for (int k = 0; k < 16; k++) {
        int n = k * 1024 + tid;
        sg[n] = fmaf(a, e[n], om * p[n]);
    }
    __syncthreads();

    float pw[16];
    float lsum = 0.f;
    #pragma unroll
    for (int k = 0; k < 16; k++) {
        int n = k * 1024 + tid;
        float v = fmaf(sh0, sg[(n + N_ - 1) & (N_ - 1)],
                 fmaf(sh1, sg[n], sh2 * sg[(n + 1) & (N_ - 1)]));
        v = __powf(v, gamma);        // shifted >= 0 by construction
        pw[k] = v;
        lsum += v;
    }

    #pragma unroll
    for (int o = 16; o; o >>= 1) lsum += __shfl_xor_sync(0xffffffffu, lsum, o);
    if ((tid & 31) == 0) sr[tid >> 5] = lsum;
    __syncthreads();
    if (tid < 32) {
        float t = sr[tid];
        #pragma unroll
        for (int o = 16; o; o >>= 1) t += __shfl_xor_sync(0xffffffffu, t, o);
        if (tid == 0) sr[32] = t;
    }
    __syncthreads();
    float invT = 1.f / (sr[32] + 1e-6f);

    float* op = out + base;
    #pragma unroll
    for (int k = 0; k < 16; k++) {
        int n = k * 1024 + tid;
        op[n] = pw[k] * invT;
    }
}

// ---------------------------------------------------------------------------
extern "C" void kernel_launch(void* const* d_in, const int* in_sizes, int n_in,
                              void* d_out, int out_size) {
    const float* cs   = (const float*)d_in[0];   // controller_state (B, D)
    const float* prev = (const float*)d_in[1];   // prev_weights (B, H, N)
    const float* mem  = (const float*)d_in[2];   // memory (B, N, W)
    const float* Wr   = (const float*)d_in[3];   // W_read (P*H, D)
    const float* br   = (const float*)d_in[4];   // b_read (P*H,)
    float* out = (float*)d_out;

    cudaFuncSetAttribute(kfinish, cudaFuncAttributeMaxDynamicSharedMemorySize,
                         N_ * sizeof(float));

    kparams<<<B_ * H_, 256>>>(cs, Wr, br);
    kdots<<<dim3(N_ / 128, B_), 128>>>(mem);
    kfinish<<<B_ * H_, 1024, N_ * sizeof(float)>>>(prev, out);
}

// round 2
// speedup vs baseline: 1.1416x; 1.1416x over previous
#include <cuda_runtime.h>
#include <math.h>

#define B_ 64
#define H_ 4
#define N_ 16384
#define W_ 64
#define D_ 1024
#define P_ 70
#define R_ 280
#define BT 8
#define RT 10

// Scratch (device globals: allocation-free rule)
__device__ float g_params[B_ * R_];      // raw GEMM output
__device__ float g_ebuf[B_ * H_ * N_];   // exp(beta * cos_sim), 16 MB
__device__ float g_kv[B_ * H_ * W_];     // key * beta / ||key||
__device__ float g_hp[B_ * H_ * 8];      // gate, sh0, sh1, sh2, gamma
__device__ float g_sum[B_ * H_];         // softmax denominators (atomic)

__device__ __forceinline__ float softplusf(float x) {
    return x > 20.f ? x : log1pf(__expf(x));
}

// sm_103a packed f32x2 FMA (2x fp32 throughput; only reachable via PTX)
__device__ __forceinline__ unsigned long long ff2(unsigned long long a,
                                                  unsigned long long b,
                                                  unsigned long long c) {
    unsigned long long d;
    asm("fma.rn.f32x2 %0, %1, %2, %3;" : "=l"(d) : "l"(a), "l"(b), "l"(c));
    return d;
}
__device__ __forceinline__ void f4pack(float4 v, unsigned long long& lo,
                                       unsigned long long& hi) {
    asm("mov.b64 %0, {%2, %3};\n\tmov.b64 %1, {%4, %5};"
        : "=l"(lo), "=l"(hi) : "f"(v.x), "f"(v.y), "f"(v.z), "f"(v.w));
}
__device__ __forceinline__ float hsum2(unsigned long long v) {
    float x, y;
    asm("mov.b64 {%0, %1}, %2;" : "=f"(x), "=f"(y) : "l"(v));
    return x + y;
}

// ---------------------------------------------------------------------------
// Kernel A: tiled GEMM. Block = (8 batches x 10 rows), warp w owns batch w.
// smem tiles cut L2 traffic 71MB -> 16MB; float4 gives 4-wide FMA ILP.
// ---------------------------------------------------------------------------
__global__ __launch_bounds__(256) void kparams(const float* __restrict__ cs,
                                               const float* __restrict__ Wr,
                                               const float* __restrict__ br) {
    extern __shared__ float4 dynp[];          // [BT*256] cs tile | [RT*256] W tile
    float4* scs = dynp;
    float4* sw  = dynp + BT * 256;
    int rt = blockIdx.x, bt = blockIdx.y;
    int tid = threadIdx.x;

    const float4* gcs = (const float4*)cs + (size_t)bt * BT * 256;
    #pragma unroll
    for (int i = 0; i < BT; i++) scs[i * 256 + tid] = gcs[i * 256 + tid];
    const float4* gw = (const float4*)Wr + (size_t)rt * RT * 256;
    #pragma unroll
    for (int i = 0; i < RT; i++) sw[i * 256 + tid] = gw[i * 256 + tid];
    __syncthreads();

    int w = tid >> 5, l = tid & 31;
    const float4* a = scs + w * 256;
    #pragma unroll
    for (int rl = 0; rl < RT; rl++) {
        const float4* bv = sw + rl * 256;
        float4 acc = make_float4(0.f, 0.f, 0.f, 0.f);
        #pragma unroll
        for (int j = 0; j < 8; j++) {
            float4 x = a[j * 32 + l], y = bv[j * 32 + l];
            acc.x = fmaf(x.x, y.x, acc.x);
            acc.y = fmaf(x.y, y.y, acc.y);
            acc.z = fmaf(x.z, y.z, acc.z);
            acc.w = fmaf(x.w, y.w, acc.w);
        }
        float s = (acc.x + acc.y) + (acc.z + acc.w);
        #pragma unroll
        for (int o = 16; o; o >>= 1) s += __shfl_xor_sync(0xffffffffu, s, o);
        if (l == 0) {
            int r = rt * RT + rl;
            g_params[(bt * BT + w) * R_ + r] = s + br[r];
        }
    }
}

// ---------------------------------------------------------------------------
// Kernel A2: one warp per (b,h): key norm + activations from raw params.
// ---------------------------------------------------------------------------
__global__ __launch_bounds__(256) void kderive() {
    int gw = (blockIdx.x * 256 + threadIdx.x) >> 5;   // 0..255 = b*4+h
    int l = threadIdx.x & 31;
    int b = gw >> 2, h = gw & 3;
    const float* ps = &g_params[b * R_ + h * P_];
    float v0 = ps[l], v1 = ps[l + 32];
    float v2 = (l < 6) ? ps[l + 64] : 0.f;

    float kn2 = fmaf(v0, v0, v1 * v1);
    #pragma unroll
    for (int o = 16; o; o >>= 1) kn2 += __shfl_xor_sync(0xffffffffu, kn2, o);

    float p64 = __shfl_sync(0xffffffffu, v2, 0);
    float p65 = __shfl_sync(0xffffffffu, v2, 1);
    float p66 = __shfl_sync(0xffffffffu, v2, 2);
    float p67 = __shfl_sync(0xffffffffu, v2, 3);
    float p68 = __shfl_sync(0xffffffffu, v2, 4);
    float p69 = __shfl_sync(0xffffffffu, v2, 5);

    float beta = softplusf(p64);
    float scale = beta / fmaxf(sqrtf(kn2), 1e-8f);
    g_kv[gw * W_ + l]      = v0 * scale;
    g_kv[gw * W_ + 32 + l] = v1 * scale;

    if (l == 0) {
        float gate = 1.f / (1.f + __expf(-p65));
        float m = fmaxf(p66, fmaxf(p67, p68));
        float e0 = __expf(p66 - m), e1 = __expf(p67 - m), e2 = __expf(p68 - m);
        float si = 1.f / (e0 + e1 + e2);
        g_hp[gw * 8 + 0] = gate;
        g_hp[gw * 8 + 1] = e0 * si;
        g_hp[gw * 8 + 2] = e1 * si;
        g_hp[gw * 8 + 3] = e2 * si;
        g_hp[gw * 8 + 4] = 1.f + softplusf(p69);
        g_sum[gw] = 0.f;            // re-zero every replay (deterministic)
    }
}

// ---------------------------------------------------------------------------
// Kernel B: stream memory once. 256 rows/block, 1 thread per row via smem
// tile (stride 17 float4 = conflict-free LDS.128). Packed f32x2 FMAs halve
// the fp32 instruction count -> fully DRAM-bound.
// ---------------------------------------------------------------------------
__global__ __launch_bounds__(256) void kdots(const float* __restrict__ mem) {
    extern __shared__ float4 dynd[];          // 256 rows * 17 float4
    __shared__ float4 skv4[H_ * 16];
    __shared__ float sred[32];
    int b = blockIdx.y;
    int n0 = blockIdx.x * 256;
    int tid = threadIdx.x;

    if (tid < H_ * 16) skv4[tid] = ((const float4*)(g_kv + b * H_ * W_))[tid];

    const float4* src = (const float4*)(mem + ((size_t)b * N_ + n0) * W_);
    #pragma unroll
    for (int j = 0; j < 16; j++) {
        int f = j * 256 + tid;
        dynd[(f >> 4) * 17 + (f & 15)] = src[f];
    }
    __syncthreads();

    unsigned long long ssq = 0, d0 = 0, d1 = 0, d2 = 0, d3 = 0;
    const float4* mr = dynd + tid * 17;
    #pragma unroll
    for (int j = 0; j < 16; j++) {
        unsigned long long mlo, mhi, klo, khi;
        f4pack(mr[j], mlo, mhi);
        f4pack(skv4[j],      klo, khi); d0 = ff2(klo, mlo, d0); d0 = ff2(khi, mhi, d0);
        f4pack(skv4[16 + j], klo, khi); d1 = ff2(klo, mlo, d1); d1 = ff2(khi, mhi, d1);
        f4pack(skv4[32 + j], klo, khi); d2 = ff2(klo, mlo, d2); d2 = ff2(khi, mhi, d2);
        f4pack(skv4[48 + j], klo, khi); d3 = ff2(klo, mlo, d3); d3 = ff2(khi, mhi, d3);
        ssq = ff2(mlo, mlo, ssq);       ssq = ff2(mhi, mhi, ssq);
    }

    float inv = 1.f / fmaxf(sqrtf(hsum2(ssq)), 1e-8f);
    float e0 = __expf(hsum2(d0) * inv);
    float e1 = __expf(hsum2(d1) * inv);
    float e2 = __expf(hsum2(d2) * inv);
    float e3 = __expf(hsum2(d3) * inv);

    size_t o = (size_t)b * (H_ * N_) + n0 + tid;
    g_ebuf[o]          = e0;
    g_ebuf[o + N_]     = e1;
    g_ebuf[o + 2 * N_] = e2;
    g_ebuf[o + 3 * N_] = e3;

    float s0 = e0, s1 = e1, s2 = e2, s3 = e3;
    #pragma unroll
    for (int off = 16; off; off >>= 1) {
        s0 += __shfl_xor_sync(0xffffffffu, s0, off);
        s1 += __shfl_xor_sync(0xffffffffu, s1, off);
        s2 += __shfl_xor_sync(0xffffffffu, s2, off);
        s3 += __shfl_xor_sync(0xffffffffu, s3, off);
    }
    if ((tid & 31) == 0) {
        int wp = tid >> 5;
        sred[wp * 4 + 0] = s0; sred[wp * 4 + 1] = s1;
        sred[wp * 4 + 2] = s2; sred[wp * 4 + 3] = s3;
    }
    __syncthreads();
    if (tid < 4) {
        float t = 0.f;
        #pragma unroll
        for (int wp = 0; wp < 8; wp++) t += sred[wp * 4 + tid];
        atomicAdd(&g_sum[b * 4 + tid], t);
    }
}

// ---------------------------------------------------------------------------
// Kernel C: one (b,h) row per block, float4 path. Neighbors via shfl (only
// warp-boundary lanes touch smem scalars). pw recomputed in pass B to stay
// <=32 regs at 2 CTAs/SM.
// ---------------------------------------------------------------------------
__global__ __launch_bounds__(1024, 2) void kfinish(const float* __restrict__ prev,
                                                   float* __restrict__ out) {
    extern __shared__ float sg[];             // N_ floats gated values
    __shared__ float sr[33];
    int bh = blockIdx.x;
    int tid = threadIdx.x;
    int lane = tid & 31;

    const float* hp = &g_hp[bh * 8];
    float gate = hp[0], sh0 = hp[1], sh1 = hp[2], sh2 = hp[3], gamma = hp[4];
    float aG = gate / g_sum[bh];
    float om = 1.f - gate;

    size_t base = (size_t)bh * N_;
    const float4* e4 = (const float4*)(g_ebuf + base);
    const float4* p4 = (const float4*)(prev + base);
    float4* sg4 = (float4*)sg;

    #pragma unroll
    for (int k = 0; k < 4; k++) {
        int i = k * 1024 + tid;
        float4 e = e4[i], p = p4[i];
        float4 g;
        g.x = fmaf(aG, e.x, om * p.x);
        g.y = fmaf(aG, e.y, om * p.y);
        g.z = fmaf(aG, e.z, om * p.z);
        g.w = fmaf(aG, e.w, om * p.w);
        sg4[i] = g;
    }
    __syncthreads();

    float lsum = 0.f;
    #pragma unroll
    for (int k = 0; k < 4; k++) {
        int i = k * 1024 + tid;
        float4 g = sg4[i];
        float left = __shfl_up_sync(0xffffffffu, g.w, 1);
        if (lane == 0) left = sg[(4 * i + N_ - 1) & (N_ - 1)];
        float right = __shfl_down_sync(0xffffffffu, g.x, 1);
        if (lane == 31) right = sg[(4 * i + 4) & (N_ - 1)];
        float v0 = fmaf(sh0, left, fmaf(sh1, g.x, sh2 * g.y));
        float v1 = fmaf(sh0, g.x, fmaf(sh1, g.y, sh2 * g.z));
        float v2 = fmaf(sh0, g.y, fmaf(sh1, g.z, sh2 * g.w));
        float v3 = fmaf(sh0, g.z, fmaf(sh1, g.w, sh2 * right));
        lsum += __powf(v0, gamma) + __powf(v1, gamma)
              + __powf(v2, gamma) + __powf(v3, gamma);
    }

    #pragma unroll
    for (int o = 16; o; o >>= 1) lsum += __shfl_xor_sync(0xffffffffu, lsum, o);
    if (lane == 0) sr[tid >> 5] = lsum;
    __syncthreads();
    if (tid < 32) {
        float t = sr[tid];
        #pragma unroll
        for (int o = 16; o; o >>= 1) t += __shfl_xor_sync(0xffffffffu, t, o);
        if (tid == 0) sr[32] = t;
    }
    __syncthreads();
    float invT = 1.f / (sr[32] + 1e-6f);

    float4* o4 = (float4*)(out + base);
    #pragma unroll
    for (int k = 0; k < 4; k++) {
        int i = k * 1024 + tid;
        float4 g = sg4[i];
        float left = __shfl_up_sync(0xffffffffu, g.w, 1);
        if (lane == 0) left = sg[(4 * i + N_ - 1) & (N_ - 1)];
        float right = __shfl_down_sync(0xffffffffu, g.x, 1);
        if (lane == 31) right = sg[(4 * i + 4) & (N_ - 1)];
        float v0 = fmaf(sh0, left, fmaf(sh1, g.x, sh2 * g.y));
        float v1 = fmaf(sh0, g.x, fmaf(sh1, g.y, sh2 * g.z));
        float v2 = fmaf(sh0, g.y, fmaf(sh1, g.z, sh2 * g.w));
        float v3 = fmaf(sh0, g.z, fmaf(sh1, g.w, sh2 * right));
        float4 r;
        r.x = __powf(v0, gamma) * invT;
        r.y = __powf(v1, gamma) * invT;
        r.z = __powf(v2, gamma) * invT;
        r.w = __powf(v3, gamma) * invT;
        o4[i] = r;
    }
}

// ---------------------------------------------------------------------------
extern "C" void kernel_launch(void* const* d_in, const int* in_sizes, int n_in,
                              void* d_out, int out_size) {
    const float* cs   = (const float*)d_in[0];   // controller_state (B, D)
    const float* prev = (const float*)d_in[1];   // prev_weights (B, H, N)
    const float* mem  = (const float*)d_in[2];   // memory (B, N, W)
    const float* Wr   = (const float*)d_in[3];   // W_read (P*H, D)
    const float* br   = (const float*)d_in[4];   // b_read (P*H,)
    float* out = (float*)d_out;

    static int inited = 0;
    if (!inited) {
        cudaFuncSetAttribute(kparams, cudaFuncAttributeMaxDynamicSharedMemorySize,
                             (BT + RT) * 256 * 16);
        cudaFuncSetAttribute(kdots, cudaFuncAttributeMaxDynamicSharedMemorySize,
                             256 * 17 * 16);
        cudaFuncSetAttribute(kfinish, cudaFuncAttributeMaxDynamicSharedMemorySize,
                             N_ * 4);
        inited = 1;
    }

    kparams<<<dim3(R_ / RT, B_ / BT), 256, (BT + RT) * 256 * 16>>>(cs, Wr, br);
    kderive<<<(B_ * H_) / 8, 256>>>();
    kdots<<<dim3(N_ / 256, B_), 256, 256 * 17 * 16>>>(mem);
    kfinish<<<B_ * H_, 1024, N_ * 4>>>(prev, out);
}